// round 9
// baseline (speedup 1.0000x reference)
#include <cuda_runtime.h>
#include <cuda_fp16.h>
#include <cstdint>

#define RESULT_ELEMS 16777216   // 64*256*32*32

// smem layout (bytes)
#define OFF_XH    0        // x hi [128][64] half swizzled, 16384
#define OFF_XL    16384    // x lo, 16384
#define OFF_EH    32768    // E chunk hi [128][64] half, 16384
#define OFF_EL    49152    // E chunk lo, 16384
#define OFF_H     65536    // 512 floats
#define OFF_BKS   67584    // 128 ints
#define SMEM_SZ   68096

__device__ float  g_h[512];        // 0.5*||e_k||^2 (exact fp32)
__device__ __half gEh[512 * 64];   // E hi, [n][k]
__device__ __half gEl[512 * 64];   // E lo, [n][k]

__device__ __forceinline__ uint32_t smem_u32(const void* p) {
    uint32_t a;
    asm("{ .reg .u64 t; cvta.to.shared.u64 t, %1; cvt.u32.u64 %0, t; }" : "=r"(a) : "l"(p));
    return a;
}
__device__ __forceinline__ uint32_t sw(uint32_t b) { return b ^ ((b >> 3) & 0x70); }

__device__ __forceinline__ void ldsm4(uint32_t r[4], uint32_t addr) {
    asm volatile("ldmatrix.sync.aligned.m8n8.x4.shared.b16 {%0,%1,%2,%3}, [%4];"
                 : "=r"(r[0]), "=r"(r[1]), "=r"(r[2]), "=r"(r[3]) : "r"(addr));
}
__device__ __forceinline__ void mma16816(float c[4], const uint32_t a[4],
                                         uint32_t b0, uint32_t b1) {
    asm volatile("mma.sync.aligned.m16n8k16.row.col.f32.f16.f16.f32 "
                 "{%0,%1,%2,%3}, {%4,%5,%6,%7}, {%8,%9}, {%0,%1,%2,%3};"
                 : "+f"(c[0]), "+f"(c[1]), "+f"(c[2]), "+f"(c[3])
                 : "r"(a[0]), "r"(a[1]), "r"(a[2]), "r"(a[3]), "r"(b0), "r"(b1));
}

// merged prep: h[k] and E hi/lo split
__global__ void prep_kernel(const float* __restrict__ w) {
    int n = threadIdx.x;   // 0..511
    float s = 0.f;
    #pragma unroll
    for (int c = 0; c < 64; ++c) {
        float v = w[c * 512 + n];
        s = fmaf(v, v, s);
        __half h = __float2half_rn(v);
        gEh[n * 64 + c] = h;
        gEl[n * 64 + c] = __float2half_rn(v - __half2float(h));
    }
    g_h[n] = 0.5f * s;
}

__global__ __launch_bounds__(256, 3)
void vq_mma(const float* __restrict__ x, const float* __restrict__ w,
            float* __restrict__ out) {
    extern __shared__ char smem[];
    const uint32_t sb = smem_u32(smem);
    float* hsm = (float*)(smem + OFF_H);
    int*   bks = (int*)(smem + OFF_BKS);

    const int tid = threadIdx.x;
    const int bg  = blockIdx.x >> 3;             // b*4+g
    const int mt  = blockIdx.x & 7;
    const int hw0 = mt * 128;

    // ---- split x tile (128 rows) to fp16 hi/lo directly, swizzled [m][k] ----
    const float* xb = x + (size_t)bg * 65536 + hw0;
    {
        int m  = tid & 127;
        int c0 = (tid >> 7) * 16;                // 16 c-pairs per half-block
        #pragma unroll
        for (int i = 0; i < 16; ++i) {
            int c2 = c0 + i;
            float v0 = xb[(size_t)(2 * c2) * 1024 + m];
            float v1 = xb[(size_t)(2 * c2 + 1) * 1024 + m];
            __half h0 = __float2half_rn(v0), h1 = __float2half_rn(v1);
            __half l0 = __float2half_rn(v0 - __half2float(h0));
            __half l1 = __float2half_rn(v1 - __half2float(h1));
            uint32_t off = sw((uint32_t)(m * 128 + c2 * 4));
            *(__half2*)(smem + OFF_XH + off) = __halves2half2(h0, h1);
            *(__half2*)(smem + OFF_XL + off) = __halves2half2(l0, l1);
        }
    }
    hsm[tid]       = g_h[tid];
    hsm[tid + 256] = g_h[tid + 256];
    __syncthreads();

    const int w8 = tid >> 5, lane = tid & 31;
    const int m0 = w8 * 16;                      // 16 rows per warp
    const int group = lane >> 2, tig = lane & 3;

    // ---- load all A fragments once: 4 ksteps x (hi,lo) = 32 regs ----
    uint32_t ah[4][4], al[4][4];
    {
        uint32_t arow = (uint32_t)(m0 + (lane & 15));
        uint32_t acol = (uint32_t)((lane >> 4) * 16);
        #pragma unroll
        for (int ks = 0; ks < 4; ++ks) {
            uint32_t off = sw(arow * 128 + (uint32_t)ks * 32 + acol);
            ldsm4(ah[ks], sb + OFF_XH + off);
            ldsm4(al[ks], sb + OFF_XL + off);
        }
    }

    float best0v = -3.4e38f, best1v = -3.4e38f;
    int   best0k = 0,        best1k = 0;

    // B row-addresses (E is [n][k], k contiguous; non-trans ldmatrix)
    const uint32_t brow_l = (uint32_t)((lane & 7) + ((lane >> 4) & 1) * 8);
    const uint32_t bcol_l = (uint32_t)(((lane >> 3) & 1) * 16);

    for (int ch = 0; ch < 4; ++ch) {
        __syncthreads();   // previous chunk's E readers done
        // ---- copy E chunk (128 codes) hi/lo into swizzled smem ----
        #pragma unroll
        for (int i = 0; i < 4; ++i) {
            int u = tid + i * 256;
            int r = u >> 3, seg = u & 7;
            uint32_t off = sw((uint32_t)(r * 128 + seg * 16));
            const char* srch = (const char*)(gEh + (ch * 128 + r) * 64) + seg * 16;
            const char* srcl = (const char*)(gEl + (ch * 128 + r) * 64) + seg * 16;
            *(uint4*)(smem + OFF_EH + off) = *(const uint4*)srch;
            *(uint4*)(smem + OFF_EL + off) = *(const uint4*)srcl;
        }
        __syncthreads();

        for (int jp = 0; jp < 8; ++jp) {       // pairs of 8-code n-tiles
            float c0[4] = {0, 0, 0, 0};
            float c1[4] = {0, 0, 0, 0};
            #pragma unroll
            for (int ks = 0; ks < 4; ++ks) {
                uint32_t boff = sw((uint32_t)(jp * 16 + brow_l) * 128 +
                                   (uint32_t)ks * 32 + bcol_l);
                uint32_t bh[4], bl[4];
                ldsm4(bh, sb + OFF_EH + boff);
                ldsm4(bl, sb + OFF_EL + boff);
                // full 4-term split: (xh+xl).(eh+el), fp32 accumulate
                mma16816(c0, ah[ks], bh[0], bh[1]);
                mma16816(c0, al[ks], bh[0], bh[1]);
                mma16816(c0, ah[ks], bl[0], bl[1]);
                mma16816(c0, al[ks], bl[0], bl[1]);
                mma16816(c1, ah[ks], bh[2], bh[3]);
                mma16816(c1, al[ks], bh[2], bh[3]);
                mma16816(c1, ah[ks], bl[2], bl[3]);
                mma16816(c1, al[ks], bl[2], bl[3]);
            }
            // ---- fused argmax: ascending n per thread, strict > ----
            int nb = ch * 128 + jp * 16;
            float h0 = hsm[nb + 2 * tig];
            float h1 = hsm[nb + 2 * tig + 1];
            float h2 = hsm[nb + 8 + 2 * tig];
            float h3 = hsm[nb + 8 + 2 * tig + 1];
            float s;
            s = c0[0] - h0; if (s > best0v) { best0v = s; best0k = nb + 2 * tig; }
            s = c0[1] - h1; if (s > best0v) { best0v = s; best0k = nb + 2 * tig + 1; }
            s = c1[0] - h2; if (s > best0v) { best0v = s; best0k = nb + 8 + 2 * tig; }
            s = c1[1] - h3; if (s > best0v) { best0v = s; best0k = nb + 8 + 2 * tig + 1; }
            s = c0[2] - h0; if (s > best1v) { best1v = s; best1k = nb + 2 * tig; }
            s = c0[3] - h1; if (s > best1v) { best1v = s; best1k = nb + 2 * tig + 1; }
            s = c1[2] - h2; if (s > best1v) { best1v = s; best1k = nb + 8 + 2 * tig; }
            s = c1[3] - h3; if (s > best1v) { best1v = s; best1k = nb + 8 + 2 * tig + 1; }
        }
    }

    // ---- reduce across the 4 lanes sharing each row (tig dimension) ----
    #pragma unroll
    for (int off = 1; off <= 2; off <<= 1) {
        float ov; int ok;
        ov = __shfl_xor_sync(0xffffffffu, best0v, off);
        ok = __shfl_xor_sync(0xffffffffu, best0k, off);
        if (ov > best0v || (ov == best0v && ok < best0k)) { best0v = ov; best0k = ok; }
        ov = __shfl_xor_sync(0xffffffffu, best1v, off);
        ok = __shfl_xor_sync(0xffffffffu, best1k, off);
        if (ov > best1v || (ov == best1v && ok < best1k)) { best1v = ov; best1k = ok; }
    }
    if (tig == 0) {
        bks[m0 + group]     = best0k;
        bks[m0 + group + 8] = best1k;
    }
    __syncthreads();

    // ---- write argmins (as float) ----
    if (tid < 128)
        out[RESULT_ELEMS + bg * 1024 + hw0 + tid] = (float)bks[tid];

    // ---- write result: out[bg*64+c][hw0+m] = w[c][k]*0.5 (coalesced over m) ----
    {
        int m = tid & 127, chh = tid >> 7;
        int k = bks[m];
        float* ob = out + (size_t)bg * 65536 + hw0 + m;
        #pragma unroll
        for (int i = 0; i < 32; ++i) {
            int c = chh + i * 2;
            ob[(size_t)c * 1024] = w[c * 512 + k] * 0.5f;
        }
    }
}

extern "C" void kernel_launch(void* const* d_in, const int* in_sizes, int n_in,
                              void* d_out, int out_size) {
    const float* x = (const float*)d_in[0];   // (64,256,32,32) fp32
    const float* w = (const float*)d_in[1];   // (64,512) fp32
    float* out = (float*)d_out;               // result ++ argmins

    cudaFuncSetAttribute(vq_mma, cudaFuncAttributeMaxDynamicSharedMemorySize, SMEM_SZ);

    prep_kernel<<<1, 512>>>(w);
    vq_mma<<<2048, 256, SMEM_SZ>>>(x, w, out);
}

// round 10
// speedup vs baseline: 1.3536x; 1.3536x over previous
#include <cuda_runtime.h>
#include <cuda_fp16.h>
#include <cstdint>

#define RESULT_ELEMS 16777216   // 64*256*32*32

// smem layout (bytes)
#define OFF_XH    0        // x hi [128][64] half swizzled, 16384
#define OFF_XL    16384    // x lo, 16384
#define OFF_EH    32768    // E chunk hi [128][64] half, 16384
#define OFF_EL    49152    // E chunk lo, 16384
#define OFF_H     65536    // 512 floats
#define OFF_BKS   67584    // 128 ints
#define SMEM_SZ   68096

__device__ float  g_h[512];        // 0.5*||e_k||^2 (exact fp32)
__device__ __half gEh[512 * 64];   // E hi, [n][k]
__device__ __half gEl[512 * 64];   // E lo, [n][k]

__device__ __forceinline__ uint32_t smem_u32(const void* p) {
    uint32_t a;
    asm("{ .reg .u64 t; cvta.to.shared.u64 t, %1; cvt.u32.u64 %0, t; }" : "=r"(a) : "l"(p));
    return a;
}
__device__ __forceinline__ uint32_t sw(uint32_t b) { return b ^ ((b >> 3) & 0x70); }

__device__ __forceinline__ void ldsm4(uint32_t r[4], uint32_t addr) {
    asm volatile("ldmatrix.sync.aligned.m8n8.x4.shared.b16 {%0,%1,%2,%3}, [%4];"
                 : "=r"(r[0]), "=r"(r[1]), "=r"(r[2]), "=r"(r[3]) : "r"(addr));
}
__device__ __forceinline__ void mma16816(float c[4], const uint32_t a[4],
                                         uint32_t b0, uint32_t b1) {
    asm volatile("mma.sync.aligned.m16n8k16.row.col.f32.f16.f16.f32 "
                 "{%0,%1,%2,%3}, {%4,%5,%6,%7}, {%8,%9}, {%0,%1,%2,%3};"
                 : "+f"(c[0]), "+f"(c[1]), "+f"(c[2]), "+f"(c[3])
                 : "r"(a[0]), "r"(a[1]), "r"(a[2]), "r"(a[3]), "r"(b0), "r"(b1));
}

// Fast prep: 16 blocks x 256 threads, coalesced loads AND stores via smem transpose.
// Block handles 32 codes (n0..n0+31). g_h uses the same sequential c=0..63 fmaf
// chain as before -> bit-identical h values.
__global__ __launch_bounds__(256) void prep_kernel(const float* __restrict__ w) {
    __shared__ float s[32][65];
    const int tid = threadIdx.x;
    const int n0  = blockIdx.x * 32;

    // load: warp-coalesced over n (32 consecutive n per warp row)
    {
        int j = tid & 31;          // n offset
        int c = tid >> 5;          // starting dim
        #pragma unroll
        for (int it = 0; it < 8; ++it, c += 8)
            s[j][c] = w[c * 512 + n0 + j];
    }
    __syncthreads();

    // h: threads 0..31, identical fmaf order as rounds 1-9
    if (tid < 32) {
        float acc = 0.f;
        #pragma unroll
        for (int c = 0; c < 64; ++c) { float v = s[tid][c]; acc = fmaf(v, v, acc); }
        g_h[n0 + tid] = 0.5f * acc;
    }

    // write: thread owns (j = tid>>3, c0 = (tid&7)*8): 8 consecutive dims -> 16B stores
    {
        int j  = tid >> 3;
        int c0 = (tid & 7) * 8;
        __half hv[8], lv[8];
        #pragma unroll
        for (int i = 0; i < 8; ++i) {
            float v = s[j][c0 + i];
            __half h = __float2half_rn(v);
            hv[i] = h;
            lv[i] = __float2half_rn(v - __half2float(h));
        }
        *(uint4*)(gEh + (n0 + j) * 64 + c0) = *(uint4*)hv;
        *(uint4*)(gEl + (n0 + j) * 64 + c0) = *(uint4*)lv;
    }
}

__global__ __launch_bounds__(256, 3)
void vq_mma(const float* __restrict__ x, const float* __restrict__ w,
            float* __restrict__ out) {
    extern __shared__ char smem[];
    const uint32_t sb = smem_u32(smem);
    float* hsm = (float*)(smem + OFF_H);
    int*   bks = (int*)(smem + OFF_BKS);

    const int tid = threadIdx.x;
    const int bg  = blockIdx.x >> 3;             // b*4+g
    const int mt  = blockIdx.x & 7;
    const int hw0 = mt * 128;

    // ---- split x tile (128 rows) to fp16 hi/lo directly, swizzled [m][k] ----
    const float* xb = x + (size_t)bg * 65536 + hw0;
    {
        int m  = tid & 127;
        int c0 = (tid >> 7) * 16;                // 16 c-pairs per half-block
        #pragma unroll
        for (int i = 0; i < 16; ++i) {
            int c2 = c0 + i;
            float v0 = xb[(size_t)(2 * c2) * 1024 + m];
            float v1 = xb[(size_t)(2 * c2 + 1) * 1024 + m];
            __half h0 = __float2half_rn(v0), h1 = __float2half_rn(v1);
            __half l0 = __float2half_rn(v0 - __half2float(h0));
            __half l1 = __float2half_rn(v1 - __half2float(h1));
            uint32_t off = sw((uint32_t)(m * 128 + c2 * 4));
            *(__half2*)(smem + OFF_XH + off) = __halves2half2(h0, h1);
            *(__half2*)(smem + OFF_XL + off) = __halves2half2(l0, l1);
        }
    }
    hsm[tid]       = g_h[tid];
    hsm[tid + 256] = g_h[tid + 256];
    __syncthreads();

    const int w8 = tid >> 5, lane = tid & 31;
    const int m0 = w8 * 16;                      // 16 rows per warp
    const int group = lane >> 2, tig = lane & 3;

    // ---- load all A fragments once: 4 ksteps x (hi,lo) = 32 regs ----
    uint32_t ah[4][4], al[4][4];
    {
        uint32_t arow = (uint32_t)(m0 + (lane & 15));
        uint32_t acol = (uint32_t)((lane >> 4) * 16);
        #pragma unroll
        for (int ks = 0; ks < 4; ++ks) {
            uint32_t off = sw(arow * 128 + (uint32_t)ks * 32 + acol);
            ldsm4(ah[ks], sb + OFF_XH + off);
            ldsm4(al[ks], sb + OFF_XL + off);
        }
    }

    float best0v = -3.4e38f, best1v = -3.4e38f;
    int   best0k = 0,        best1k = 0;

    // B row-addresses (E is [n][k], k contiguous; non-trans ldmatrix)
    const uint32_t brow_l = (uint32_t)((lane & 7) + ((lane >> 4) & 1) * 8);
    const uint32_t bcol_l = (uint32_t)(((lane >> 3) & 1) * 16);

    for (int ch = 0; ch < 4; ++ch) {
        __syncthreads();   // previous chunk's E readers done
        // ---- copy E chunk (128 codes) hi/lo into swizzled smem ----
        #pragma unroll
        for (int i = 0; i < 4; ++i) {
            int u = tid + i * 256;
            int r = u >> 3, seg = u & 7;
            uint32_t off = sw((uint32_t)(r * 128 + seg * 16));
            const char* srch = (const char*)(gEh + (ch * 128 + r) * 64) + seg * 16;
            const char* srcl = (const char*)(gEl + (ch * 128 + r) * 64) + seg * 16;
            *(uint4*)(smem + OFF_EH + off) = *(const uint4*)srch;
            *(uint4*)(smem + OFF_EL + off) = *(const uint4*)srcl;
        }
        __syncthreads();

        for (int jp = 0; jp < 8; ++jp) {       // pairs of 8-code n-tiles
            float c0[4] = {0, 0, 0, 0};
            float c1[4] = {0, 0, 0, 0};
            #pragma unroll
            for (int ks = 0; ks < 4; ++ks) {
                uint32_t boff = sw((uint32_t)(jp * 16 + brow_l) * 128 +
                                   (uint32_t)ks * 32 + bcol_l);
                uint32_t bh[4], bl[4];
                ldsm4(bh, sb + OFF_EH + boff);
                ldsm4(bl, sb + OFF_EL + boff);
                // full 4-term split: (xh+xl).(eh+el), fp32 accumulate
                mma16816(c0, ah[ks], bh[0], bh[1]);
                mma16816(c0, al[ks], bh[0], bh[1]);
                mma16816(c0, ah[ks], bl[0], bl[1]);
                mma16816(c0, al[ks], bl[0], bl[1]);
                mma16816(c1, ah[ks], bh[2], bh[3]);
                mma16816(c1, al[ks], bh[2], bh[3]);
                mma16816(c1, ah[ks], bl[2], bl[3]);
                mma16816(c1, al[ks], bl[2], bl[3]);
            }
            // ---- fused argmax: ascending n per thread, strict > ----
            int nb = ch * 128 + jp * 16;
            float h0 = hsm[nb + 2 * tig];
            float h1 = hsm[nb + 2 * tig + 1];
            float h2 = hsm[nb + 8 + 2 * tig];
            float h3 = hsm[nb + 8 + 2 * tig + 1];
            float s;
            s = c0[0] - h0; if (s > best0v) { best0v = s; best0k = nb + 2 * tig; }
            s = c0[1] - h1; if (s > best0v) { best0v = s; best0k = nb + 2 * tig + 1; }
            s = c1[0] - h2; if (s > best0v) { best0v = s; best0k = nb + 8 + 2 * tig; }
            s = c1[1] - h3; if (s > best0v) { best0v = s; best0k = nb + 8 + 2 * tig + 1; }
            s = c0[2] - h0; if (s > best1v) { best1v = s; best1k = nb + 2 * tig; }
            s = c0[3] - h1; if (s > best1v) { best1v = s; best1k = nb + 2 * tig + 1; }
            s = c1[2] - h2; if (s > best1v) { best1v = s; best1k = nb + 8 + 2 * tig; }
            s = c1[3] - h3; if (s > best1v) { best1v = s; best1k = nb + 8 + 2 * tig + 1; }
        }
    }

    // ---- reduce across the 4 lanes sharing each row (tig dimension) ----
    #pragma unroll
    for (int off = 1; off <= 2; off <<= 1) {
        float ov; int ok;
        ov = __shfl_xor_sync(0xffffffffu, best0v, off);
        ok = __shfl_xor_sync(0xffffffffu, best0k, off);
        if (ov > best0v || (ov == best0v && ok < best0k)) { best0v = ov; best0k = ok; }
        ov = __shfl_xor_sync(0xffffffffu, best1v, off);
        ok = __shfl_xor_sync(0xffffffffu, best1k, off);
        if (ov > best1v || (ov == best1v && ok < best1k)) { best1v = ov; best1k = ok; }
    }
    if (tig == 0) {
        bks[m0 + group]     = best0k;
        bks[m0 + group + 8] = best1k;
    }
    __syncthreads();

    // ---- write argmins (as float) ----
    if (tid < 128)
        out[RESULT_ELEMS + bg * 1024 + hw0 + tid] = (float)bks[tid];

    // ---- write result: out[bg*64+c][hw0+m] = w[c][k]*0.5 (coalesced over m) ----
    {
        int m = tid & 127, chh = tid >> 7;
        int k = bks[m];
        float* ob = out + (size_t)bg * 65536 + hw0 + m;
        #pragma unroll
        for (int i = 0; i < 32; ++i) {
            int c = chh + i * 2;
            ob[(size_t)c * 1024] = w[c * 512 + k] * 0.5f;
        }
    }
}

extern "C" void kernel_launch(void* const* d_in, const int* in_sizes, int n_in,
                              void* d_out, int out_size) {
    const float* x = (const float*)d_in[0];   // (64,256,32,32) fp32
    const float* w = (const float*)d_in[1];   // (64,512) fp32
    float* out = (float*)d_out;               // result ++ argmins

    cudaFuncSetAttribute(vq_mma, cudaFuncAttributeMaxDynamicSharedMemorySize, SMEM_SZ);

    prep_kernel<<<16, 256>>>(w);
    vq_mma<<<2048, 256, SMEM_SZ>>>(x, w, out);
}

// round 11
// speedup vs baseline: 1.3573x; 1.0028x over previous
#include <cuda_runtime.h>
#include <cuda_fp16.h>
#include <cstdint>

#define RESULT_ELEMS 16777216   // 64*256*32*32

// smem layout (bytes)
#define OFF_XH    0        // x hi [128][64] half swizzled, 16384
#define OFF_XL    16384    // x lo, 16384
#define OFF_EH    32768    // E chunk hi [128][64] half, 16384
#define OFF_EL    49152    // E chunk lo, 16384
#define OFF_H     65536    // 512 floats
#define OFF_BKS   67584    // 128 ints
#define SMEM_SZ   68096

__device__ float  g_h[512];        // 0.5*||e_k||^2 (exact fp32)
__device__ __half gEh[512 * 64];   // E hi, [n][k]
__device__ __half gEl[512 * 64];   // E lo, [n][k]

__device__ __forceinline__ uint32_t smem_u32(const void* p) {
    uint32_t a;
    asm("{ .reg .u64 t; cvta.to.shared.u64 t, %1; cvt.u32.u64 %0, t; }" : "=r"(a) : "l"(p));
    return a;
}
__device__ __forceinline__ uint32_t sw(uint32_t b) { return b ^ ((b >> 3) & 0x70); }

__device__ __forceinline__ void ldsm4(uint32_t r[4], uint32_t addr) {
    asm volatile("ldmatrix.sync.aligned.m8n8.x4.shared.b16 {%0,%1,%2,%3}, [%4];"
                 : "=r"(r[0]), "=r"(r[1]), "=r"(r[2]), "=r"(r[3]) : "r"(addr));
}
__device__ __forceinline__ void mma16816(float c[4], const uint32_t a[4],
                                         uint32_t b0, uint32_t b1) {
    asm volatile("mma.sync.aligned.m16n8k16.row.col.f32.f16.f16.f32 "
                 "{%0,%1,%2,%3}, {%4,%5,%6,%7}, {%8,%9}, {%0,%1,%2,%3};"
                 : "+f"(c[0]), "+f"(c[1]), "+f"(c[2]), "+f"(c[3])
                 : "r"(a[0]), "r"(a[1]), "r"(a[2]), "r"(a[3]), "r"(b0), "r"(b1));
}

// Fast prep: 16 blocks x 256 threads, coalesced loads AND stores via smem transpose.
__global__ __launch_bounds__(256) void prep_kernel(const float* __restrict__ w) {
    __shared__ float s[32][65];
    const int tid = threadIdx.x;
    const int n0  = blockIdx.x * 32;

    {
        int j = tid & 31;          // n offset
        int c = tid >> 5;          // starting dim
        #pragma unroll
        for (int it = 0; it < 8; ++it, c += 8)
            s[j][c] = w[c * 512 + n0 + j];
    }
    __syncthreads();

    if (tid < 32) {
        float acc = 0.f;
        #pragma unroll
        for (int c = 0; c < 64; ++c) { float v = s[tid][c]; acc = fmaf(v, v, acc); }
        g_h[n0 + tid] = 0.5f * acc;
    }

    {
        int j  = tid >> 3;
        int c0 = (tid & 7) * 8;
        __half hv[8], lv[8];
        #pragma unroll
        for (int i = 0; i < 8; ++i) {
            float v = s[j][c0 + i];
            __half h = __float2half_rn(v);
            hv[i] = h;
            lv[i] = __float2half_rn(v - __half2float(h));
        }
        *(uint4*)(gEh + (n0 + j) * 64 + c0) = *(uint4*)hv;
        *(uint4*)(gEl + (n0 + j) * 64 + c0) = *(uint4*)lv;
    }
}

__global__ __launch_bounds__(256, 3)
void vq_mma(const float* __restrict__ x, const float* __restrict__ w,
            float* __restrict__ out) {
    extern __shared__ char smem[];
    const uint32_t sb = smem_u32(smem);
    float* hsm = (float*)(smem + OFF_H);
    int*   bks = (int*)(smem + OFF_BKS);

    const int tid = threadIdx.x;
    const int bg  = blockIdx.x >> 3;             // b*4+g
    const int mt  = blockIdx.x & 7;
    const int hw0 = mt * 128;

    // ---- split x tile (128 rows) to fp16 hi/lo directly, swizzled [m][k] ----
    const float* xb = x + (size_t)bg * 65536 + hw0;
    {
        int m  = tid & 127;
        int c0 = (tid >> 7) * 16;                // 16 c-pairs per half-block
        #pragma unroll
        for (int i = 0; i < 16; ++i) {
            int c2 = c0 + i;
            float v0 = xb[(size_t)(2 * c2) * 1024 + m];
            float v1 = xb[(size_t)(2 * c2 + 1) * 1024 + m];
            __half h0 = __float2half_rn(v0), h1 = __float2half_rn(v1);
            __half l0 = __float2half_rn(v0 - __half2float(h0));
            __half l1 = __float2half_rn(v1 - __half2float(h1));
            uint32_t off = sw((uint32_t)(m * 128 + c2 * 4));
            *(__half2*)(smem + OFF_XH + off) = __halves2half2(h0, h1);
            *(__half2*)(smem + OFF_XL + off) = __halves2half2(l0, l1);
        }
    }
    hsm[tid]       = g_h[tid];
    hsm[tid + 256] = g_h[tid + 256];
    __syncthreads();

    const int w8 = tid >> 5, lane = tid & 31;
    const int m0 = w8 * 16;                      // 16 rows per warp
    const int group = lane >> 2, tig = lane & 3;

    // ---- load all A fragments once: 4 ksteps x (hi,lo) = 32 regs ----
    uint32_t ah[4][4], al[4][4];
    {
        uint32_t arow = (uint32_t)(m0 + (lane & 15));
        uint32_t acol = (uint32_t)((lane >> 4) * 16);
        #pragma unroll
        for (int ks = 0; ks < 4; ++ks) {
            uint32_t off = sw(arow * 128 + (uint32_t)ks * 32 + acol);
            ldsm4(ah[ks], sb + OFF_XH + off);
            ldsm4(al[ks], sb + OFF_XL + off);
        }
    }

    float best0v = -3.4e38f, best1v = -3.4e38f;
    int   best0k = 0,        best1k = 0;

    // B row-addresses (E is [n][k], k contiguous; non-trans ldmatrix)
    const uint32_t brow_l = (uint32_t)((lane & 7) + ((lane >> 4) & 1) * 8);
    const uint32_t bcol_l = (uint32_t)(((lane >> 3) & 1) * 16);

    for (int ch = 0; ch < 4; ++ch) {
        __syncthreads();   // previous chunk's E readers done
        // ---- copy E chunk (128 codes) hi/lo into swizzled smem ----
        #pragma unroll
        for (int i = 0; i < 4; ++i) {
            int u = tid + i * 256;
            int r = u >> 3, seg = u & 7;
            uint32_t off = sw((uint32_t)(r * 128 + seg * 16));
            const char* srch = (const char*)(gEh + (ch * 128 + r) * 64) + seg * 16;
            const char* srcl = (const char*)(gEl + (ch * 128 + r) * 64) + seg * 16;
            *(uint4*)(smem + OFF_EH + off) = *(const uint4*)srch;
            *(uint4*)(smem + OFF_EL + off) = *(const uint4*)srcl;
        }
        __syncthreads();

        for (int jp = 0; jp < 8; ++jp) {       // pairs of 8-code n-tiles
            float c0[4] = {0, 0, 0, 0};
            float c1[4] = {0, 0, 0, 0};
            #pragma unroll
            for (int ks = 0; ks < 4; ++ks) {
                uint32_t boff = sw((uint32_t)(jp * 16 + brow_l) * 128 +
                                   (uint32_t)ks * 32 + bcol_l);
                uint32_t bh[4], bl[4];
                ldsm4(bh, sb + OFF_EH + boff);
                ldsm4(bl, sb + OFF_EL + boff);
                // 4-term split, c0/c1 chains INTERLEAVED (same per-acc order
                // as before -> bit-identical sums; doubles same-acc distance)
                mma16816(c0, ah[ks], bh[0], bh[1]);
                mma16816(c1, ah[ks], bh[2], bh[3]);
                mma16816(c0, al[ks], bh[0], bh[1]);
                mma16816(c1, al[ks], bh[2], bh[3]);
                mma16816(c0, ah[ks], bl[0], bl[1]);
                mma16816(c1, ah[ks], bl[2], bl[3]);
                mma16816(c0, al[ks], bl[0], bl[1]);
                mma16816(c1, al[ks], bl[2], bl[3]);
            }
            // ---- fused argmax: ascending n per thread, strict > ----
            int nb = ch * 128 + jp * 16;
            float h0 = hsm[nb + 2 * tig];
            float h1 = hsm[nb + 2 * tig + 1];
            float h2 = hsm[nb + 8 + 2 * tig];
            float h3 = hsm[nb + 8 + 2 * tig + 1];
            float s;
            s = c0[0] - h0; if (s > best0v) { best0v = s; best0k = nb + 2 * tig; }
            s = c0[1] - h1; if (s > best0v) { best0v = s; best0k = nb + 2 * tig + 1; }
            s = c1[0] - h2; if (s > best0v) { best0v = s; best0k = nb + 8 + 2 * tig; }
            s = c1[1] - h3; if (s > best0v) { best0v = s; best0k = nb + 8 + 2 * tig + 1; }
            s = c0[2] - h0; if (s > best1v) { best1v = s; best1k = nb + 2 * tig; }
            s = c0[3] - h1; if (s > best1v) { best1v = s; best1k = nb + 2 * tig + 1; }
            s = c1[2] - h2; if (s > best1v) { best1v = s; best1k = nb + 8 + 2 * tig; }
            s = c1[3] - h3; if (s > best1v) { best1v = s; best1k = nb + 8 + 2 * tig + 1; }
        }
    }

    // ---- reduce across the 4 lanes sharing each row (tig dimension) ----
    #pragma unroll
    for (int off = 1; off <= 2; off <<= 1) {
        float ov; int ok;
        ov = __shfl_xor_sync(0xffffffffu, best0v, off);
        ok = __shfl_xor_sync(0xffffffffu, best0k, off);
        if (ov > best0v || (ov == best0v && ok < best0k)) { best0v = ov; best0k = ok; }
        ov = __shfl_xor_sync(0xffffffffu, best1v, off);
        ok = __shfl_xor_sync(0xffffffffu, best1k, off);
        if (ov > best1v || (ov == best1v && ok < best1k)) { best1v = ov; best1k = ok; }
    }
    if (tig == 0) {
        bks[m0 + group]     = best0k;
        bks[m0 + group + 8] = best1k;
    }
    __syncthreads();

    // ---- write argmins (as float) ----
    if (tid < 128)
        out[RESULT_ELEMS + bg * 1024 + hw0 + tid] = (float)bks[tid];

    // ---- write result: out[bg*64+c][hw0+m] = w[c][k]*0.5 (coalesced over m) ----
    {
        int m = tid & 127, chh = tid >> 7;
        int k = bks[m];
        float* ob = out + (size_t)bg * 65536 + hw0 + m;
        #pragma unroll
        for (int i = 0; i < 32; ++i) {
            int c = chh + i * 2;
            ob[(size_t)c * 1024] = w[c * 512 + k] * 0.5f;
        }
    }
}

extern "C" void kernel_launch(void* const* d_in, const int* in_sizes, int n_in,
                              void* d_out, int out_size) {
    const float* x = (const float*)d_in[0];   // (64,256,32,32) fp32
    const float* w = (const float*)d_in[1];   // (64,512) fp32
    float* out = (float*)d_out;               // result ++ argmins

    cudaFuncSetAttribute(vq_mma, cudaFuncAttributeMaxDynamicSharedMemorySize, SMEM_SZ);

    prep_kernel<<<16, 256>>>(w);
    vq_mma<<<2048, 256, SMEM_SZ>>>(x, w, out);
}

// round 12
// speedup vs baseline: 1.5761x; 1.1612x over previous
#include <cuda_runtime.h>
#include <cuda_fp16.h>
#include <cstdint>

#define RESULT_ELEMS 16777216   // 64*256*32*32

// smem layout (bytes)
#define OFF_XH    0        // x hi [128][64] half swizzled, 16384
#define OFF_XL    16384    // x lo, 16384
#define OFF_EH    32768    // E chunk hi [128][64] half, 16384
#define OFF_EL    49152    // E chunk lo, 16384
#define OFF_H     65536    // 512 floats
#define OFF_BKS   67584    // 128 ints
#define SMEM_SZ   68096

__device__ float  g_h[512];        // 0.5*||e_k||^2 (exact fp32)
__device__ __half gEh[512 * 64];   // E hi, [n][k]
__device__ __half gEl[512 * 64];   // E lo, [n][k]

__device__ __forceinline__ uint32_t smem_u32(const void* p) {
    uint32_t a;
    asm("{ .reg .u64 t; cvta.to.shared.u64 t, %1; cvt.u32.u64 %0, t; }" : "=r"(a) : "l"(p));
    return a;
}
__device__ __forceinline__ uint32_t sw(uint32_t b) { return b ^ ((b >> 3) & 0x70); }

__device__ __forceinline__ void ldsm4(uint32_t r[4], uint32_t addr) {
    asm volatile("ldmatrix.sync.aligned.m8n8.x4.shared.b16 {%0,%1,%2,%3}, [%4];"
                 : "=r"(r[0]), "=r"(r[1]), "=r"(r[2]), "=r"(r[3]) : "r"(addr));
}
__device__ __forceinline__ void mma16816(float c[4], const uint32_t a[4],
                                         uint32_t b0, uint32_t b1) {
    asm volatile("mma.sync.aligned.m16n8k16.row.col.f32.f16.f16.f32 "
                 "{%0,%1,%2,%3}, {%4,%5,%6,%7}, {%8,%9}, {%0,%1,%2,%3};"
                 : "+f"(c[0]), "+f"(c[1]), "+f"(c[2]), "+f"(c[3])
                 : "r"(a[0]), "r"(a[1]), "r"(a[2]), "r"(a[3]), "r"(b0), "r"(b1));
}

// Fast prep: 16 blocks x 256 threads, coalesced loads AND stores via smem transpose.
__global__ __launch_bounds__(256) void prep_kernel(const float* __restrict__ w) {
    __shared__ float s[32][65];
    const int tid = threadIdx.x;
    const int n0  = blockIdx.x * 32;

    {
        int j = tid & 31;          // n offset
        int c = tid >> 5;          // starting dim
        #pragma unroll
        for (int it = 0; it < 8; ++it, c += 8)
            s[j][c] = w[c * 512 + n0 + j];
    }
    __syncthreads();

    if (tid < 32) {
        float acc = 0.f;
        #pragma unroll
        for (int c = 0; c < 64; ++c) { float v = s[tid][c]; acc = fmaf(v, v, acc); }
        g_h[n0 + tid] = 0.5f * acc;
    }

    {
        int j  = tid >> 3;
        int c0 = (tid & 7) * 8;
        __half hv[8], lv[8];
        #pragma unroll
        for (int i = 0; i < 8; ++i) {
            float v = s[j][c0 + i];
            __half h = __float2half_rn(v);
            hv[i] = h;
            lv[i] = __float2half_rn(v - __half2float(h));
        }
        *(uint4*)(gEh + (n0 + j) * 64 + c0) = *(uint4*)hv;
        *(uint4*)(gEl + (n0 + j) * 64 + c0) = *(uint4*)lv;
    }
}

__global__ __launch_bounds__(256, 3)
void vq_mma(const float* __restrict__ x, const float* __restrict__ w,
            float* __restrict__ out) {
    extern __shared__ char smem[];
    const uint32_t sb = smem_u32(smem);
    float* hsm = (float*)(smem + OFF_H);
    int*   bks = (int*)(smem + OFF_BKS);

    const int tid = threadIdx.x;
    const int bg  = blockIdx.x >> 3;             // b*4+g
    const int mt  = blockIdx.x & 7;
    const int hw0 = mt * 128;

    // ---- split x tile (128 rows) to fp16 hi/lo directly, swizzled [m][k] ----
    const float* xb = x + (size_t)bg * 65536 + hw0;
    {
        int m  = tid & 127;
        int c0 = (tid >> 7) * 16;                // 16 c-pairs per half-block
        #pragma unroll
        for (int i = 0; i < 16; ++i) {
            int c2 = c0 + i;
            float v0 = xb[(size_t)(2 * c2) * 1024 + m];
            float v1 = xb[(size_t)(2 * c2 + 1) * 1024 + m];
            __half h0 = __float2half_rn(v0), h1 = __float2half_rn(v1);
            __half l0 = __float2half_rn(v0 - __half2float(h0));
            __half l1 = __float2half_rn(v1 - __half2float(h1));
            uint32_t off = sw((uint32_t)(m * 128 + c2 * 4));
            *(__half2*)(smem + OFF_XH + off) = __halves2half2(h0, h1);
            *(__half2*)(smem + OFF_XL + off) = __halves2half2(l0, l1);
        }
    }
    hsm[tid]       = g_h[tid];
    hsm[tid + 256] = g_h[tid + 256];
    __syncthreads();

    const int w8 = tid >> 5, lane = tid & 31;
    const int m0 = w8 * 16;                      // 16 rows per warp
    const int group = lane >> 2, tig = lane & 3;

    // ---- load all A fragments once: 4 ksteps x (hi,lo) = 32 regs ----
    uint32_t ah[4][4], al[4][4];
    {
        uint32_t arow = (uint32_t)(m0 + (lane & 15));
        uint32_t acol = (uint32_t)((lane >> 4) * 16);
        #pragma unroll
        for (int ks = 0; ks < 4; ++ks) {
            uint32_t off = sw(arow * 128 + (uint32_t)ks * 32 + acol);
            ldsm4(ah[ks], sb + OFF_XH + off);
            ldsm4(al[ks], sb + OFF_XL + off);
        }
    }

    float best0v = -3.4e38f, best1v = -3.4e38f;
    int   best0k = 0,        best1k = 0;

    // B row-addresses (E is [n][k], k contiguous; non-trans ldmatrix)
    const uint32_t brow_l = (uint32_t)((lane & 7) + ((lane >> 4) & 1) * 8);
    const uint32_t bcol_l = (uint32_t)(((lane >> 3) & 1) * 16);

    for (int ch = 0; ch < 4; ++ch) {
        __syncthreads();   // previous chunk's E readers done
        // ---- copy E chunk (128 codes) hi/lo into swizzled smem ----
        #pragma unroll
        for (int i = 0; i < 4; ++i) {
            int u = tid + i * 256;
            int r = u >> 3, seg = u & 7;
            uint32_t off = sw((uint32_t)(r * 128 + seg * 16));
            const char* srch = (const char*)(gEh + (ch * 128 + r) * 64) + seg * 16;
            const char* srcl = (const char*)(gEl + (ch * 128 + r) * 64) + seg * 16;
            *(uint4*)(smem + OFF_EH + off) = *(const uint4*)srch;
            *(uint4*)(smem + OFF_EL + off) = *(const uint4*)srcl;
        }
        __syncthreads();

        for (int jp = 0; jp < 8; ++jp) {       // pairs of 8-code n-tiles
            float c0[4] = {0, 0, 0, 0};
            float c1[4] = {0, 0, 0, 0};
            #pragma unroll
            for (int ks = 0; ks < 4; ++ks) {
                uint32_t boff = sw((uint32_t)(jp * 16 + brow_l) * 128 +
                                   (uint32_t)ks * 32 + bcol_l);
                uint32_t bh[4], bl[4];
                ldsm4(bh, sb + OFF_EH + boff);
                ldsm4(bl, sb + OFF_EL + boff);
                // 3-term split: xh.eh + xl.eh + xh.el  (lo.lo dropped;
                // residual ~5e-8 rms, far below the tolerated margin)
                mma16816(c0, ah[ks], bh[0], bh[1]);
                mma16816(c1, ah[ks], bh[2], bh[3]);
                mma16816(c0, al[ks], bh[0], bh[1]);
                mma16816(c1, al[ks], bh[2], bh[3]);
                mma16816(c0, ah[ks], bl[0], bl[1]);
                mma16816(c1, ah[ks], bl[2], bl[3]);
            }
            // ---- fused argmax: ascending n per thread, strict > ----
            int nb = ch * 128 + jp * 16;
            float h0 = hsm[nb + 2 * tig];
            float h1 = hsm[nb + 2 * tig + 1];
            float h2 = hsm[nb + 8 + 2 * tig];
            float h3 = hsm[nb + 8 + 2 * tig + 1];
            float s;
            s = c0[0] - h0; if (s > best0v) { best0v = s; best0k = nb + 2 * tig; }
            s = c0[1] - h1; if (s > best0v) { best0v = s; best0k = nb + 2 * tig + 1; }
            s = c1[0] - h2; if (s > best0v) { best0v = s; best0k = nb + 8 + 2 * tig; }
            s = c1[1] - h3; if (s > best0v) { best0v = s; best0k = nb + 8 + 2 * tig + 1; }
            s = c0[2] - h0; if (s > best1v) { best1v = s; best1k = nb + 2 * tig; }
            s = c0[3] - h1; if (s > best1v) { best1v = s; best1k = nb + 2 * tig + 1; }
            s = c1[2] - h2; if (s > best1v) { best1v = s; best1k = nb + 8 + 2 * tig; }
            s = c1[3] - h3; if (s > best1v) { best1v = s; best1k = nb + 8 + 2 * tig + 1; }
        }
    }

    // ---- reduce across the 4 lanes sharing each row (tig dimension) ----
    #pragma unroll
    for (int off = 1; off <= 2; off <<= 1) {
        float ov; int ok;
        ov = __shfl_xor_sync(0xffffffffu, best0v, off);
        ok = __shfl_xor_sync(0xffffffffu, best0k, off);
        if (ov > best0v || (ov == best0v && ok < best0k)) { best0v = ov; best0k = ok; }
        ov = __shfl_xor_sync(0xffffffffu, best1v, off);
        ok = __shfl_xor_sync(0xffffffffu, best1k, off);
        if (ov > best1v || (ov == best1v && ok < best1k)) { best1v = ov; best1k = ok; }
    }
    if (tig == 0) {
        bks[m0 + group]     = best0k;
        bks[m0 + group + 8] = best1k;
    }
    __syncthreads();

    // ---- write argmins (as float) ----
    if (tid < 128)
        out[RESULT_ELEMS + bg * 1024 + hw0 + tid] = (float)bks[tid];

    // ---- write result: out[bg*64+c][hw0+m] = w[c][k]*0.5 (coalesced over m) ----
    {
        int m = tid & 127, chh = tid >> 7;
        int k = bks[m];
        float* ob = out + (size_t)bg * 65536 + hw0 + m;
        #pragma unroll
        for (int i = 0; i < 32; ++i) {
            int c = chh + i * 2;
            ob[(size_t)c * 1024] = w[c * 512 + k] * 0.5f;
        }
    }
}

extern "C" void kernel_launch(void* const* d_in, const int* in_sizes, int n_in,
                              void* d_out, int out_size) {
    const float* x = (const float*)d_in[0];   // (64,256,32,32) fp32
    const float* w = (const float*)d_in[1];   // (64,512) fp32
    float* out = (float*)d_out;               // result ++ argmins

    cudaFuncSetAttribute(vq_mma, cudaFuncAttributeMaxDynamicSharedMemorySize, SMEM_SZ);

    prep_kernel<<<16, 256>>>(w);
    vq_mma<<<2048, 256, SMEM_SZ>>>(x, w, out);
}

// round 13
// speedup vs baseline: 1.6960x; 1.0761x over previous
#include <cuda_runtime.h>
#include <cuda_fp16.h>
#include <cstdint>

#define RESULT_ELEMS 16777216   // 64*256*32*32

// smem layout (bytes)
#define OFF_XH    0        // x hi [128][64] half swizzled, 16384
#define OFF_XL    16384    // x lo, 16384
#define OFF_EB    32768    // E double buffer: buf b at +b*16384 (EH 8KB ++ EL 8KB)
#define OFF_H     65536    // 512 floats
#define OFF_BKS   67584    // 128 ints
#define SMEM_SZ   68096

__device__ float  g_h[512];        // 0.5*||e_k||^2 (exact fp32)
__device__ __half gEh[512 * 64];   // E hi, [n][k]
__device__ __half gEl[512 * 64];   // E lo, [n][k]

__device__ __forceinline__ uint32_t smem_u32(const void* p) {
    uint32_t a;
    asm("{ .reg .u64 t; cvta.to.shared.u64 t, %1; cvt.u32.u64 %0, t; }" : "=r"(a) : "l"(p));
    return a;
}
__device__ __forceinline__ uint32_t sw(uint32_t b) { return b ^ ((b >> 3) & 0x70); }

__device__ __forceinline__ void cpasync16(uint32_t dst, const void* src) {
    asm volatile("cp.async.cg.shared.global [%0], [%1], 16;"
                 :: "r"(dst), "l"(src) : "memory");
}
#define CP_COMMIT() asm volatile("cp.async.commit_group;" ::: "memory")
#define CP_WAIT1()  asm volatile("cp.async.wait_group 1;" ::: "memory")

__device__ __forceinline__ void ldsm4(uint32_t r[4], uint32_t addr) {
    asm volatile("ldmatrix.sync.aligned.m8n8.x4.shared.b16 {%0,%1,%2,%3}, [%4];"
                 : "=r"(r[0]), "=r"(r[1]), "=r"(r[2]), "=r"(r[3]) : "r"(addr));
}
__device__ __forceinline__ void mma16816(float c[4], const uint32_t a[4],
                                         uint32_t b0, uint32_t b1) {
    asm volatile("mma.sync.aligned.m16n8k16.row.col.f32.f16.f16.f32 "
                 "{%0,%1,%2,%3}, {%4,%5,%6,%7}, {%8,%9}, {%0,%1,%2,%3};"
                 : "+f"(c[0]), "+f"(c[1]), "+f"(c[2]), "+f"(c[3])
                 : "r"(a[0]), "r"(a[1]), "r"(a[2]), "r"(a[3]), "r"(b0), "r"(b1));
}

// Fast prep: 16 blocks x 256 threads, coalesced loads AND stores via smem transpose.
__global__ __launch_bounds__(256) void prep_kernel(const float* __restrict__ w) {
    __shared__ float s[32][65];
    const int tid = threadIdx.x;
    const int n0  = blockIdx.x * 32;

    {
        int j = tid & 31;
        int c = tid >> 5;
        #pragma unroll
        for (int it = 0; it < 8; ++it, c += 8)
            s[j][c] = w[c * 512 + n0 + j];
    }
    __syncthreads();

    if (tid < 32) {
        float acc = 0.f;
        #pragma unroll
        for (int c = 0; c < 64; ++c) { float v = s[tid][c]; acc = fmaf(v, v, acc); }
        g_h[n0 + tid] = 0.5f * acc;
    }

    {
        int j  = tid >> 3;
        int c0 = (tid & 7) * 8;
        __half hv[8], lv[8];
        #pragma unroll
        for (int i = 0; i < 8; ++i) {
            float v = s[j][c0 + i];
            __half h = __float2half_rn(v);
            hv[i] = h;
            lv[i] = __float2half_rn(v - __half2float(h));
        }
        *(uint4*)(gEh + (n0 + j) * 64 + c0) = *(uint4*)hv;
        *(uint4*)(gEl + (n0 + j) * 64 + c0) = *(uint4*)lv;
    }
}

__global__ __launch_bounds__(256, 3)
void vq_mma(const float* __restrict__ x, const float* __restrict__ w,
            float* __restrict__ out) {
    extern __shared__ char smem[];
    const uint32_t sb = smem_u32(smem);
    float* hsm = (float*)(smem + OFF_H);
    int*   bks = (int*)(smem + OFF_BKS);

    const int tid = threadIdx.x;
    const int bg  = blockIdx.x >> 3;             // b*4+g
    const int mt  = blockIdx.x & 7;
    const int hw0 = mt * 128;

    // ---- kick off async copy of E chunk 0 (64 codes) ----
    {
        #pragma unroll
        for (int i = 0; i < 2; ++i) {
            int u = tid + i * 256;
            int r = u >> 3, seg = u & 7;
            uint32_t off = sw((uint32_t)(r * 128 + seg * 16));
            cpasync16(sb + OFF_EB + off,        (const char*)(gEh + r * 64) + seg * 16);
            cpasync16(sb + OFF_EB + 8192 + off, (const char*)(gEl + r * 64) + seg * 16);
        }
        CP_COMMIT();
    }

    // ---- split x tile (128 rows) to fp16 hi/lo directly, swizzled [m][k] ----
    const float* xb = x + (size_t)bg * 65536 + hw0;
    {
        int m  = tid & 127;
        int c0 = (tid >> 7) * 16;
        #pragma unroll
        for (int i = 0; i < 16; ++i) {
            int c2 = c0 + i;
            float v0 = xb[(size_t)(2 * c2) * 1024 + m];
            float v1 = xb[(size_t)(2 * c2 + 1) * 1024 + m];
            __half h0 = __float2half_rn(v0), h1 = __float2half_rn(v1);
            __half l0 = __float2half_rn(v0 - __half2float(h0));
            __half l1 = __float2half_rn(v1 - __half2float(h1));
            uint32_t off = sw((uint32_t)(m * 128 + c2 * 4));
            *(__half2*)(smem + OFF_XH + off) = __halves2half2(h0, h1);
            *(__half2*)(smem + OFF_XL + off) = __halves2half2(l0, l1);
        }
    }
    hsm[tid]       = g_h[tid];
    hsm[tid + 256] = g_h[tid + 256];
    __syncthreads();

    const int w8 = tid >> 5, lane = tid & 31;
    const int m0 = w8 * 16;                      // 16 rows per warp
    const int group = lane >> 2, tig = lane & 3;

    // ---- load all A fragments once: 4 ksteps x (hi,lo) = 32 regs ----
    uint32_t ah[4][4], al[4][4];
    {
        uint32_t arow = (uint32_t)(m0 + (lane & 15));
        uint32_t acol = (uint32_t)((lane >> 4) * 16);
        #pragma unroll
        for (int ks = 0; ks < 4; ++ks) {
            uint32_t off = sw(arow * 128 + (uint32_t)ks * 32 + acol);
            ldsm4(ah[ks], sb + OFF_XH + off);
            ldsm4(al[ks], sb + OFF_XL + off);
        }
    }

    float best0v = -3.4e38f, best1v = -3.4e38f;
    int   best0k = 0,        best1k = 0;

    // B row-addresses (E is [n][k], k contiguous; non-trans ldmatrix)
    const uint32_t brow_l = (uint32_t)((lane & 7) + ((lane >> 4) & 1) * 8);
    const uint32_t bcol_l = (uint32_t)(((lane >> 3) & 1) * 16);

    #pragma unroll 1
    for (int ch = 0; ch < 8; ++ch) {             // 8 chunks of 64 codes
        // issue next chunk's copy into the other buffer (hazard-free: that
        // buffer's compute finished before the trailing barrier last iter)
        if (ch < 7) {
            uint32_t dst = sb + OFF_EB + (uint32_t)((ch + 1) & 1) * 16384;
            #pragma unroll
            for (int i = 0; i < 2; ++i) {
                int u = tid + i * 256;
                int r = u >> 3, seg = u & 7;
                uint32_t off = sw((uint32_t)(r * 128 + seg * 16));
                cpasync16(dst + off,        (const char*)(gEh + ((ch + 1) * 64 + r) * 64) + seg * 16);
                cpasync16(dst + 8192 + off, (const char*)(gEl + ((ch + 1) * 64 + r) * 64) + seg * 16);
            }
        }
        CP_COMMIT();      // empty group when ch==7 keeps the wait immediate uniform
        CP_WAIT1();       // chunk ch's data has landed
        __syncthreads();

        const uint32_t ebase = sb + OFF_EB + (uint32_t)(ch & 1) * 16384;

        #pragma unroll
        for (int jp = 0; jp < 4; ++jp) {         // pairs of 8-code n-tiles
            float c0[4] = {0, 0, 0, 0};
            float c1[4] = {0, 0, 0, 0};
            #pragma unroll
            for (int ks = 0; ks < 4; ++ks) {
                uint32_t boff = sw((uint32_t)(jp * 16 + brow_l) * 128 +
                                   (uint32_t)ks * 32 + bcol_l);
                uint32_t bh[4], bl[4];
                ldsm4(bh, ebase + boff);
                ldsm4(bl, ebase + 8192 + boff);
                // 3-term split: xh.eh + xl.eh + xh.el
                mma16816(c0, ah[ks], bh[0], bh[1]);
                mma16816(c1, ah[ks], bh[2], bh[3]);
                mma16816(c0, al[ks], bh[0], bh[1]);
                mma16816(c1, al[ks], bh[2], bh[3]);
                mma16816(c0, ah[ks], bl[0], bl[1]);
                mma16816(c1, ah[ks], bl[2], bl[3]);
            }
            // ---- fused argmax: ascending n per thread, strict > ----
            int nb = ch * 64 + jp * 16;
            float h0 = hsm[nb + 2 * tig];
            float h1 = hsm[nb + 2 * tig + 1];
            float h2 = hsm[nb + 8 + 2 * tig];
            float h3 = hsm[nb + 8 + 2 * tig + 1];
            float s;
            s = c0[0] - h0; if (s > best0v) { best0v = s; best0k = nb + 2 * tig; }
            s = c0[1] - h1; if (s > best0v) { best0v = s; best0k = nb + 2 * tig + 1; }
            s = c1[0] - h2; if (s > best0v) { best0v = s; best0k = nb + 8 + 2 * tig; }
            s = c1[1] - h3; if (s > best0v) { best0v = s; best0k = nb + 8 + 2 * tig + 1; }
            s = c0[2] - h0; if (s > best1v) { best1v = s; best1k = nb + 2 * tig; }
            s = c0[3] - h1; if (s > best1v) { best1v = s; best1k = nb + 2 * tig + 1; }
            s = c1[2] - h2; if (s > best1v) { best1v = s; best1k = nb + 8 + 2 * tig; }
            s = c1[3] - h3; if (s > best1v) { best1v = s; best1k = nb + 8 + 2 * tig + 1; }
        }
        __syncthreads();  // all warps done with buf (ch&1) before it is overwritten
    }

    // ---- reduce across the 4 lanes sharing each row (tig dimension) ----
    #pragma unroll
    for (int off = 1; off <= 2; off <<= 1) {
        float ov; int ok;
        ov = __shfl_xor_sync(0xffffffffu, best0v, off);
        ok = __shfl_xor_sync(0xffffffffu, best0k, off);
        if (ov > best0v || (ov == best0v && ok < best0k)) { best0v = ov; best0k = ok; }
        ov = __shfl_xor_sync(0xffffffffu, best1v, off);
        ok = __shfl_xor_sync(0xffffffffu, best1k, off);
        if (ov > best1v || (ov == best1v && ok < best1k)) { best1v = ov; best1k = ok; }
    }
    if (tig == 0) {
        bks[m0 + group]     = best0k;
        bks[m0 + group + 8] = best1k;
    }
    __syncthreads();

    // ---- write argmins (as float) ----
    if (tid < 128)
        out[RESULT_ELEMS + bg * 1024 + hw0 + tid] = (float)bks[tid];

    // ---- write result: out[bg*64+c][hw0+m] = w[c][k]*0.5 (coalesced over m) ----
    {
        int m = tid & 127, chh = tid >> 7;
        int k = bks[m];
        float* ob = out + (size_t)bg * 65536 + hw0 + m;
        #pragma unroll
        for (int i = 0; i < 32; ++i) {
            int c = chh + i * 2;
            ob[(size_t)c * 1024] = w[c * 512 + k] * 0.5f;
        }
    }
}

extern "C" void kernel_launch(void* const* d_in, const int* in_sizes, int n_in,
                              void* d_out, int out_size) {
    const float* x = (const float*)d_in[0];   // (64,256,32,32) fp32
    const float* w = (const float*)d_in[1];   // (64,512) fp32
    float* out = (float*)d_out;               // result ++ argmins

    cudaFuncSetAttribute(vq_mma, cudaFuncAttributeMaxDynamicSharedMemorySize, SMEM_SZ);

    prep_kernel<<<16, 256>>>(w);
    vq_mma<<<2048, 256, SMEM_SZ>>>(x, w, out);
}